// round 1
// baseline (speedup 1.0000x reference)
#include <cuda_runtime.h>
#include <cstdint>

#define HIDDEN   128
#define OUT      256
#define NRAD     6
#define NODES_MAX 50176
#define TM       128
#define ASTRIDE  260   // 128-row activation tile stride (conflict-shaped)
#define BSTRIDE  264   // 32-row weight stage stride (8*k + g banks distinct)

// 25.6 MB node accumulator scratch (allocation-free rule: __device__ global)
__device__ float g_hbuf[(size_t)NODES_MAX * HIDDEN];
__device__ int   g_is64;

__device__ __forceinline__ uint32_t tf32r(float x) {
    uint32_t r;
    asm("cvt.rna.tf32.f32 %0, %1;" : "=r"(r) : "f"(x));
    return r;
}

// ---------------------------------------------------------------------------
// Index dtype detection: if the buffer is int32, reading it as int64 gives
// lo + hi*2^32 with hi a random node id (nonzero w.p. ~1-2e-5 per element).
// 64 probes => misdetection probability ~0. Deterministic on fixed inputs.
// ---------------------------------------------------------------------------
__global__ void detect_kernel(const long long* __restrict__ idx, int n_nodes) {
    if (threadIdx.x == 0 && blockIdx.x == 0) {
        int ok = 1;
        for (int k = 0; k < 64; k++) {
            long long v = idx[k];
            if (v < 0 || v >= (long long)n_nodes) { ok = 0; break; }
        }
        g_is64 = ok;
    }
}

// ---------------------------------------------------------------------------
// Edge phase: one warp per edge. Lane l owns columns [4l, 4l+4).
// g = (rbf @ W_rbf) * x, scatter-added with red.global.add.v4.f32 (L2 atomics).
// ---------------------------------------------------------------------------
__global__ void scatter_kernel(const float* __restrict__ x,
                               const float* __restrict__ rbf,
                               const void*  __restrict__ idxp,
                               const float* __restrict__ W_rbf,
                               int E) {
    const int lane = threadIdx.x & 31;
    const int c0   = lane * 4;

    float w[NRAD][4];
#pragma unroll
    for (int r = 0; r < NRAD; r++)
#pragma unroll
        for (int j = 0; j < 4; j++)
            w[r][j] = __ldg(&W_rbf[r * HIDDEN + c0 + j]);

    const bool is64 = (g_is64 != 0);
    const long long* i64 = (const long long*)idxp;
    const int*       i32 = (const int*)idxp;

    int warp  = (blockIdx.x * blockDim.x + threadIdx.x) >> 5;
    int nwarp = (gridDim.x * blockDim.x) >> 5;

    for (int e = warp; e < E; e += nwarp) {
        long long node = is64 ? __ldg(&i64[e]) : (long long)__ldg(&i32[e]);
        const float* rp = rbf + (size_t)e * NRAD;
        float r0 = __ldg(rp + 0), r1 = __ldg(rp + 1), r2 = __ldg(rp + 2);
        float r3 = __ldg(rp + 3), r4 = __ldg(rp + 4), r5 = __ldg(rp + 5);
        // streaming load of x: evict-first so L2 stays for the atomics
        float4 xv = __ldcs((const float4*)(x + (size_t)e * HIDDEN + c0));

        float d[4];
#pragma unroll
        for (int j = 0; j < 4; j++) {
            float s = r0 * w[0][j];
            s = fmaf(r1, w[1][j], s);
            s = fmaf(r2, w[2][j], s);
            s = fmaf(r3, w[3][j], s);
            s = fmaf(r4, w[4][j], s);
            s = fmaf(r5, w[5][j], s);
            d[j] = s;
        }
        float g0 = d[0] * xv.x, g1 = d[1] * xv.y;
        float g2 = d[2] * xv.z, g3 = d[3] * xv.w;

        float* dst = g_hbuf + (size_t)node * HIDDEN + c0;
        asm volatile("red.global.add.v4.f32 [%0], {%1,%2,%3,%4};"
                     :: "l"(dst), "f"(g0), "f"(g1), "f"(g2), "f"(g3) : "memory");
    }
}

// ---------------------------------------------------------------------------
// Fused 4-layer MLP on tf32 tensor-core mma.sync.
// CTA tile: 128 rows x 256 cols. 8 warps in a 2(M) x 4(N) grid; each warp
// owns a 64x64 C tile = 4 m16 x 8 n8 fragments (128 fp32 accum regs/thread).
// Activations live in SMEM (tf32-prerounded bits), overwritten in place per
// layer; weights staged 32 K-rows at a time.
// ---------------------------------------------------------------------------
__device__ __forceinline__ void mma8(float* c, const uint32_t* a, const uint32_t* b) {
    asm volatile("mma.sync.aligned.m16n8k8.row.col.f32.tf32.tf32.f32 "
                 "{%0,%1,%2,%3}, {%4,%5,%6,%7}, {%8,%9}, {%0,%1,%2,%3};"
                 : "+f"(c[0]), "+f"(c[1]), "+f"(c[2]), "+f"(c[3])
                 : "r"(a[0]), "r"(a[1]), "r"(a[2]), "r"(a[3]),
                   "r"(b[0]), "r"(b[1]));
}

__global__ __launch_bounds__(256, 1)
void mlp_kernel(const float* __restrict__ W_down,
                const float* __restrict__ Ws,
                const float* __restrict__ bs,
                float* __restrict__ out,
                int n_nodes) {
    extern __shared__ float smem[];
    uint32_t* As = (uint32_t*)smem;                  // [TM][ASTRIDE]
    uint32_t* Bs = (uint32_t*)(smem + TM * ASTRIDE); // [32][BSTRIDE]

    const int tid  = threadIdx.x;
    const int row0 = blockIdx.x * TM;

    // Load input tile (128 x 128) from node accumulator, preround to tf32.
    for (int t = tid; t < TM * (HIDDEN / 4); t += 256) {
        int r  = t >> 5;
        int c4 = (t & 31) << 2;
        float4 v = make_float4(0.f, 0.f, 0.f, 0.f);
        if (row0 + r < n_nodes)
            v = *(const float4*)(g_hbuf + (size_t)(row0 + r) * HIDDEN + c4);
        uint32_t* d = As + r * ASTRIDE + c4;
        d[0] = tf32r(v.x); d[1] = tf32r(v.y); d[2] = tf32r(v.z); d[3] = tf32r(v.w);
    }
    __syncthreads();

    const int lane = tid & 31;
    const int w    = tid >> 5;
    const int wm   = (w & 1) << 6;   // warp row offset (0/64)
    const int wn   = (w >> 1) << 6;  // warp col offset (0/64/128/192)
    const int g    = lane >> 2;
    const int q    = lane & 3;

    for (int layer = 0; layer < 4; layer++) {
        const int K = (layer == 0) ? HIDDEN : OUT;
        const float* W = (layer == 0) ? W_down : (Ws + (size_t)(layer - 1) * OUT * OUT);

        float C[4][8][4];
#pragma unroll
        for (int mi = 0; mi < 4; mi++)
#pragma unroll
            for (int ni = 0; ni < 8; ni++)
#pragma unroll
                for (int j = 0; j < 4; j++) C[mi][ni][j] = 0.f;

        for (int k0 = 0; k0 < K; k0 += 32) {
            // stage 32 x 256 weight chunk (coalesced, tf32 prerounded)
            for (int t = tid; t < 32 * (OUT / 4); t += 256) {
                int kk = t >> 6;
                int n4 = (t & 63) << 2;
                float4 v = *(const float4*)(W + (size_t)(k0 + kk) * OUT + n4);
                uint32_t* d = Bs + kk * BSTRIDE + n4;
                d[0] = tf32r(v.x); d[1] = tf32r(v.y); d[2] = tf32r(v.z); d[3] = tf32r(v.w);
            }
            __syncthreads();

#pragma unroll
            for (int ks = 0; ks < 32; ks += 8) {
                uint32_t a[4][4];
#pragma unroll
                for (int mi = 0; mi < 4; mi++) {
                    int r  = wm + mi * 16 + g;
                    int kc = k0 + ks + q;
                    a[mi][0] = As[r * ASTRIDE + kc];
                    a[mi][1] = As[(r + 8) * ASTRIDE + kc];
                    a[mi][2] = As[r * ASTRIDE + kc + 4];
                    a[mi][3] = As[(r + 8) * ASTRIDE + kc + 4];
                }
                uint32_t b[8][2];
#pragma unroll
                for (int ni = 0; ni < 8; ni++) {
                    int c = wn + ni * 8 + g;
                    b[ni][0] = Bs[(ks + q) * BSTRIDE + c];
                    b[ni][1] = Bs[(ks + q + 4) * BSTRIDE + c];
                }
#pragma unroll
                for (int mi = 0; mi < 4; mi++)
#pragma unroll
                    for (int ni = 0; ni < 8; ni++)
                        mma8(C[mi][ni], a[mi], b[ni]);
            }
            __syncthreads();  // before restaging Bs
        }

        float bias[8][2];
        if (layer > 0) {
            const float* bp = bs + (size_t)(layer - 1) * OUT;
#pragma unroll
            for (int ni = 0; ni < 8; ni++) {
                int c = wn + ni * 8 + (q << 1);
                bias[ni][0] = __ldg(bp + c);
                bias[ni][1] = __ldg(bp + c + 1);
            }
        }

        // Epilogue: bias + SiLU (layers 1-3), write back to As (layers 0-2)
        // or to gmem (layer 3). In-place As overwrite is safe: all warps
        // passed the k-loop's trailing __syncthreads and C is in registers.
#pragma unroll
        for (int mi = 0; mi < 4; mi++) {
#pragma unroll
            for (int ni = 0; ni < 8; ni++) {
#pragma unroll
                for (int j = 0; j < 4; j++) {
                    int r = wm + mi * 16 + g + ((j >> 1) << 3);
                    int c = wn + ni * 8 + (q << 1) + (j & 1);
                    float v = C[mi][ni][j];
                    if (layer > 0) {
                        v += bias[ni][j & 1];
                        v = v / (1.f + __expf(-v));   // SiLU
                    }
                    if (layer < 3) {
                        As[r * ASTRIDE + c] = tf32r(v);
                    } else if (row0 + r < n_nodes) {
                        out[(size_t)(row0 + r) * OUT + c] = v;
                    }
                }
            }
        }
        __syncthreads();
    }
}

// ---------------------------------------------------------------------------
extern "C" void kernel_launch(void* const* d_in, const int* in_sizes, int n_in,
                              void* d_out, int out_size) {
    const float* x      = (const float*)d_in[0];
    const float* rbf    = (const float*)d_in[1];
    const void*  idx    = d_in[2];
    const float* W_rbf  = (const float*)d_in[3];
    const float* W_down = (const float*)d_in[4];
    const float* Ws     = (const float*)d_in[5];
    const float* bs     = (const float*)d_in[6];
    float* out = (float*)d_out;

    const int E       = in_sizes[0] / HIDDEN;
    const int n_nodes = out_size / OUT;

    void* hbuf_ptr = nullptr;
    cudaGetSymbolAddress(&hbuf_ptr, g_hbuf);
    cudaMemsetAsync(hbuf_ptr, 0, (size_t)n_nodes * HIDDEN * sizeof(float));

    detect_kernel<<<1, 32>>>((const long long*)idx, n_nodes);
    scatter_kernel<<<2048, 256>>>(x, rbf, idx, W_rbf, E);

    const int smem_bytes = (TM * ASTRIDE + 32 * BSTRIDE) * (int)sizeof(float);
    cudaFuncSetAttribute(mlp_kernel, cudaFuncAttributeMaxDynamicSharedMemorySize, smem_bytes);
    const int grid = (n_nodes + TM - 1) / TM;
    mlp_kernel<<<grid, 256, smem_bytes>>>(W_down, Ws, bs, out, n_nodes);
}

// round 9
// speedup vs baseline: 1.1595x; 1.1595x over previous
#include <cuda_runtime.h>
#include <cstdint>

#define HIDDEN   128
#define OUT      256
#define NRAD     6
#define TM       128
#define KCH      32
#define ASTRIDE  260   // activation tile stride (banks: 260%32=4 -> conflict-free frags)
#define BSTRIDE  264   // weight stage stride   (banks: 264%32=8 -> conflict-free frags)
#define CHUNK_WORDS (OUT * KCH)   // 8192 words = 32KB chunk
#define NCHUNKS  28               // 4 (layer0 K=128) + 3*8 (K=256)
#define NODES_MAX 50176

__device__ float    g_hbuf[(size_t)NODES_MAX * HIDDEN];  // scatter accumulator
__device__ uint32_t g_wt[(size_t)NCHUNKS * CHUNK_WORDS]; // tf32-prerounded weights [chunk][k][n]
__device__ int      g_is64;

__device__ __forceinline__ uint32_t tf32r(float x) {
    uint32_t r; asm("cvt.rna.tf32.f32 %0, %1;" : "=r"(r) : "f"(x)); return r;
}
__device__ __forceinline__ void cp_async16(uint32_t dst_smem, const void* src) {
    asm volatile("cp.async.cg.shared.global [%0], [%1], 16;" :: "r"(dst_smem), "l"(src) : "memory");
}
__device__ __forceinline__ void cp_commit() {
    asm volatile("cp.async.commit_group;" ::: "memory");
}
template <int N>
__device__ __forceinline__ void cp_wait() {
    asm volatile("cp.async.wait_group %0;" :: "n"(N) : "memory");
}
__device__ __forceinline__ uint32_t smem_u32(const void* p) {
    uint32_t a;
    asm("{ .reg .u64 t; cvta.to.shared.u64 t, %1; cvt.u32.u64 %0, t; }" : "=r"(a) : "l"(p));
    return a;
}
__device__ __forceinline__ void mma8(float* c, const uint32_t* a, const uint32_t* b) {
    asm volatile("mma.sync.aligned.m16n8k8.row.col.f32.tf32.tf32.f32 "
                 "{%0,%1,%2,%3}, {%4,%5,%6,%7}, {%8,%9}, {%0,%1,%2,%3};"
                 : "+f"(c[0]), "+f"(c[1]), "+f"(c[2]), "+f"(c[3])
                 : "r"(a[0]), "r"(a[1]), "r"(a[2]), "r"(a[3]),
                   "r"(b[0]), "r"(b[1]));
}

// ---------------------------------------------------------------------------
// prep: (a) block 0 warp 0 detects index dtype; (b) pre-round all MLP weights
// to tf32 bits in chunk-major layout [chunk][k(0..31)][n(0..255)].
// ---------------------------------------------------------------------------
__global__ void prep_kernel(const float* __restrict__ Wd, const float* __restrict__ Ws,
                            const long long* __restrict__ idx, int n_nodes) {
    if (blockIdx.x == 0 && threadIdx.x < 32) {
        long long v = idx[threadIdx.x];
        unsigned ok = __ballot_sync(0xFFFFFFFFu, v >= 0 && v < (long long)n_nodes);
        if (threadIdx.x == 0) g_is64 = (ok == 0xFFFFFFFFu) ? 1 : 0;
    }
    int u = blockIdx.x * blockDim.x + threadIdx.x;
    if (u >= NCHUNKS * CHUNK_WORDS) return;
    int gch = u / CHUNK_WORDS;
    int rem = u % CHUNK_WORDS;
    int k   = rem >> 8;          // 0..31
    int n   = rem & 255;         // 0..255
    int layer, c;
    if (gch < 4) { layer = 0; c = gch; } else { layer = 1 + (gch - 4) / 8; c = (gch - 4) % 8; }
    int kg = c * KCH + k;
    float v = (layer == 0) ? Wd[kg * OUT + n]
                           : Ws[(size_t)(layer - 1) * OUT * OUT + (size_t)kg * OUT + n];
    g_wt[u] = tf32r(v);
}

// ---------------------------------------------------------------------------
// edge scatter: one warp per edge, red.global.add.v4.f32 into g_hbuf
// ---------------------------------------------------------------------------
__global__ void scatter_kernel(const float* __restrict__ x,
                               const float* __restrict__ rbf,
                               const void*  __restrict__ idxp,
                               const float* __restrict__ W_rbf,
                               int E) {
    const int lane = threadIdx.x & 31;
    const int c0   = lane * 4;
    float w[NRAD][4];
#pragma unroll
    for (int r = 0; r < NRAD; r++)
#pragma unroll
        for (int j = 0; j < 4; j++) w[r][j] = __ldg(&W_rbf[r * HIDDEN + c0 + j]);

    const bool is64 = (g_is64 != 0);
    const long long* i64 = (const long long*)idxp;
    const int*       i32 = (const int*)idxp;
    int warp  = (blockIdx.x * blockDim.x + threadIdx.x) >> 5;
    int nwarp = (gridDim.x * blockDim.x) >> 5;

    for (int e = warp; e < E; e += nwarp) {
        long long node = is64 ? __ldg(&i64[e]) : (long long)__ldg(&i32[e]);
        const float* rp = rbf + (size_t)e * NRAD;
        float r0 = __ldg(rp + 0), r1 = __ldg(rp + 1), r2 = __ldg(rp + 2);
        float r3 = __ldg(rp + 3), r4 = __ldg(rp + 4), r5 = __ldg(rp + 5);
        float4 xv = __ldcs((const float4*)(x + (size_t)e * HIDDEN + c0));
        float d[4];
#pragma unroll
        for (int j = 0; j < 4; j++) {
            float s = r0 * w[0][j];
            s = fmaf(r1, w[1][j], s); s = fmaf(r2, w[2][j], s);
            s = fmaf(r3, w[3][j], s); s = fmaf(r4, w[4][j], s);
            s = fmaf(r5, w[5][j], s);
            d[j] = s;
        }
        float g0 = d[0]*xv.x, g1 = d[1]*xv.y, g2 = d[2]*xv.z, g3 = d[3]*xv.w;
        float* dst = g_hbuf + (size_t)node * HIDDEN + c0;
        asm volatile("red.global.add.v4.f32 [%0], {%1,%2,%3,%4};"
                     :: "l"(dst), "f"(g0), "f"(g1), "f"(g2), "f"(g3) : "memory");
    }
}

// ---------------------------------------------------------------------------
// fused 4-layer MLP, mma.sync tf32, cp.async double-buffered weight staging.
// CTA tile 128x256, 8 warps in 2(M)x4(N); warp C tile 64x64.
// ---------------------------------------------------------------------------
__global__ __launch_bounds__(256, 1)
void mlp_kernel(const float* __restrict__ bs, float* __restrict__ out, int n_nodes) {
    extern __shared__ float smem[];
    uint32_t* As = (uint32_t*)smem;                           // [128][ASTRIDE]
    uint32_t* Bs = (uint32_t*)(smem + TM * ASTRIDE);          // [2][32][BSTRIDE]
    const uint32_t bs_smem = smem_u32(Bs);

    const int tid  = threadIdx.x;
    const int row0 = blockIdx.x * TM;

    // load + preround activation tile
    for (int t = tid; t < TM * (HIDDEN / 4); t += 256) {
        int r  = t >> 5;
        int c4 = (t & 31) << 2;
        float4 v = make_float4(0.f, 0.f, 0.f, 0.f);
        if (row0 + r < n_nodes)
            v = *(const float4*)(g_hbuf + (size_t)(row0 + r) * HIDDEN + c4);
        uint32_t* d = As + r * ASTRIDE + c4;
        d[0] = tf32r(v.x); d[1] = tf32r(v.y); d[2] = tf32r(v.z); d[3] = tf32r(v.w);
    }
    __syncthreads();

    const int lane = tid & 31;
    const int w    = tid >> 5;
    const int wm   = (w & 1) << 6;
    const int wn   = (w >> 1) << 6;
    const int g    = lane >> 2;
    const int q    = lane & 3;

    // per-thread cp.async job: 8 x 16B, idx = tid + j*256; row = idx>>6, c16 = idx&63
    auto stage = [&](int gchunk, int buf) {
        const char* src = (const char*)(g_wt + (size_t)gchunk * CHUNK_WORDS);
#pragma unroll
        for (int j = 0; j < 8; j++) {
            int idx  = tid + j * 256;
            int row  = idx >> 6;
            int c16  = idx & 63;
            uint32_t dst = bs_smem + (uint32_t)(buf * 32 * BSTRIDE + row * BSTRIDE) * 4 + c16 * 16;
            cp_async16(dst, src + row * 1024 + c16 * 16);
        }
        cp_commit();
    };

    for (int layer = 0; layer < 4; layer++) {
        const int K   = (layer == 0) ? HIDDEN : OUT;
        const int nch = K / KCH;
        const int cb  = (layer == 0) ? 0 : (4 + (layer - 1) * 8);

        float C[4][8][4];
#pragma unroll
        for (int mi = 0; mi < 4; mi++)
#pragma unroll
            for (int ni = 0; ni < 8; ni++)
#pragma unroll
                for (int j = 0; j < 4; j++) C[mi][ni][j] = 0.f;

        stage(cb, 0);
        for (int c = 0; c < nch; c++) {
            const int buf = c & 1;
            if (c + 1 < nch) { stage(cb + c + 1, buf ^ 1); cp_wait<1>(); }
            else             { cp_wait<0>(); }
            __syncthreads();

            const uint32_t* B = Bs + buf * 32 * BSTRIDE;
#pragma unroll
            for (int ks = 0; ks < KCH; ks += 8) {
                const int k0 = c * KCH;
                uint32_t a[4][4];
#pragma unroll
                for (int mi = 0; mi < 4; mi++) {
                    int r  = wm + mi * 16 + g;
                    int kc = k0 + ks + q;
                    a[mi][0] = As[r * ASTRIDE + kc];
                    a[mi][1] = As[(r + 8) * ASTRIDE + kc];
                    a[mi][2] = As[r * ASTRIDE + kc + 4];
                    a[mi][3] = As[(r + 8) * ASTRIDE + kc + 4];
                }
                uint32_t b[8][2];
#pragma unroll
                for (int ni = 0; ni < 8; ni++) {
                    int cc = wn + ni * 8 + g;
                    b[ni][0] = B[(ks + q) * BSTRIDE + cc];
                    b[ni][1] = B[(ks + q + 4) * BSTRIDE + cc];
                }
#pragma unroll
                for (int mi = 0; mi < 4; mi++)
#pragma unroll
                    for (int ni = 0; ni < 8; ni++)
                        mma8(C[mi][ni], a[mi], b[ni]);
            }
            __syncthreads();   // buf consumed; safe for restage at c+2
        }

        float bias[8][2];
        if (layer > 0) {
            const float* bp = bs + (size_t)(layer - 1) * OUT;
#pragma unroll
            for (int ni = 0; ni < 8; ni++) {
                int cc = wn + ni * 8 + (q << 1);
                bias[ni][0] = __ldg(bp + cc);
                bias[ni][1] = __ldg(bp + cc + 1);
            }
        }

        // epilogue: bias + SiLU (layers 1-3); write back to As (0-2) or gmem (3)
#pragma unroll
        for (int mi = 0; mi < 4; mi++) {
#pragma unroll
            for (int ni = 0; ni < 8; ni++) {
#pragma unroll
                for (int j = 0; j < 4; j++) {
                    int r = wm + mi * 16 + g + ((j >> 1) << 3);
                    int cc = wn + ni * 8 + (q << 1) + (j & 1);
                    float v = C[mi][ni][j];
                    if (layer > 0) {
                        v += bias[ni][j & 1];
                        v = v / (1.f + __expf(-v));
                    }
                    if (layer < 3) {
                        As[r * ASTRIDE + cc] = tf32r(v);
                    } else if (row0 + r < n_nodes) {
                        out[(size_t)(row0 + r) * OUT + cc] = v;
                    }
                }
            }
        }
        __syncthreads();
    }
}

// ---------------------------------------------------------------------------
extern "C" void kernel_launch(void* const* d_in, const int* in_sizes, int n_in,
                              void* d_out, int out_size) {
    const float* x      = (const float*)d_in[0];
    const float* rbf    = (const float*)d_in[1];
    const void*  idx    = d_in[2];
    const float* W_rbf  = (const float*)d_in[3];
    const float* W_down = (const float*)d_in[4];
    const float* Ws     = (const float*)d_in[5];
    const float* bs     = (const float*)d_in[6];
    float* out = (float*)d_out;

    const int E       = in_sizes[0] / HIDDEN;
    const int n_nodes = out_size / OUT;

    void* hbuf_ptr = nullptr;
    cudaGetSymbolAddress(&hbuf_ptr, g_hbuf);
    cudaMemsetAsync(hbuf_ptr, 0, (size_t)n_nodes * HIDDEN * sizeof(float));

    prep_kernel<<<(NCHUNKS * CHUNK_WORDS + 255) / 256, 256>>>(
        W_down, Ws, (const long long*)idx, n_nodes);
    scatter_kernel<<<2048, 256>>>(x, rbf, idx, W_rbf, E);

    const int smem_bytes = (TM * ASTRIDE + 2 * 32 * BSTRIDE) * (int)sizeof(float);
    cudaFuncSetAttribute(mlp_kernel, cudaFuncAttributeMaxDynamicSharedMemorySize, smem_bytes);
    const int grid = (n_nodes + TM - 1) / TM;
    mlp_kernel<<<grid, 256, smem_bytes>>>(bs, out, n_nodes);
}

// round 12
// speedup vs baseline: 1.4293x; 1.2327x over previous
#include <cuda_runtime.h>
#include <cuda_fp16.h>
#include <cstdint>

#define HIDDEN   128
#define OUT      256
#define NRAD     6
#define TM       128
#define KCH      32                 // K elements per chunk
#define KPC      (KCH/2)            // 16 k-pairs per chunk
#define ASTRIDE2 132   // u32 stride, mod 32 = 4 -> a-frag banks 4g+q distinct
#define BSTRIDE2 264   // u32 stride (>=256 cols!), mod 32 = 8 -> b-frag banks 8q+g distinct
#define CHUNK_U32 (KPC * OUT)       // 4096 u32 = 16KB per chunk image
#define NCHUNKS  28                 // 4 (layer0 K=128) + 3*8 (K=256)
#define NODES_MAX 50176

__device__ float    g_hbuf[(size_t)NODES_MAX * HIDDEN];   // scatter accumulator
__device__ uint32_t g_wt[(size_t)NCHUNKS * CHUNK_U32];    // fp16x2 weights [chunk][kpair][n]
__device__ int      g_is64;

__device__ __forceinline__ void cp_async16(uint32_t dst_smem, const void* src) {
    asm volatile("cp.async.cg.shared.global [%0], [%1], 16;" :: "r"(dst_smem), "l"(src) : "memory");
}
__device__ __forceinline__ void cp_commit() {
    asm volatile("cp.async.commit_group;" ::: "memory");
}
template <int N>
__device__ __forceinline__ void cp_wait() {
    asm volatile("cp.async.wait_group %0;" :: "n"(N) : "memory");
}
__device__ __forceinline__ uint32_t smem_u32(const void* p) {
    uint32_t a;
    asm("{ .reg .u64 t; cvta.to.shared.u64 t, %1; cvt.u32.u64 %0, t; }" : "=r"(a) : "l"(p));
    return a;
}
// m16n8k16 fp16 inputs, fp32 accumulate
__device__ __forceinline__ void mma16(float* c, const uint32_t* a, const uint32_t* b) {
    asm volatile("mma.sync.aligned.m16n8k16.row.col.f32.f16.f16.f32 "
                 "{%0,%1,%2,%3}, {%4,%5,%6,%7}, {%8,%9}, {%0,%1,%2,%3};"
                 : "+f"(c[0]), "+f"(c[1]), "+f"(c[2]), "+f"(c[3])
                 : "r"(a[0]), "r"(a[1]), "r"(a[2]), "r"(a[3]),
                   "r"(b[0]), "r"(b[1]));
}
__device__ __forceinline__ uint32_t pack_h2(float lo, float hi) {
    __half2 h = __floats2half2_rn(lo, hi);
    return *(uint32_t*)&h;
}

// ---------------------------------------------------------------------------
// prep: (a) index dtype detection; (b) weights -> fp16x2 k-pair-packed chunk
// images: g_wt[chunk][kpair][n] = half2(W[k0+2kp][n], W[k0+2kp+1][n]).
// ---------------------------------------------------------------------------
__global__ void prep_kernel(const float* __restrict__ Wd, const float* __restrict__ Ws,
                            const long long* __restrict__ idx, int n_nodes) {
    if (blockIdx.x == 0 && threadIdx.x < 32) {
        long long v = idx[threadIdx.x];
        unsigned ok = __ballot_sync(0xFFFFFFFFu, v >= 0 && v < (long long)n_nodes);
        if (threadIdx.x == 0) g_is64 = (ok == 0xFFFFFFFFu) ? 1 : 0;
    }
    int u = blockIdx.x * blockDim.x + threadIdx.x;
    if (u >= NCHUNKS * CHUNK_U32) return;
    int gch = u / CHUNK_U32;
    int rem = u % CHUNK_U32;
    int kp  = rem >> 8;          // 0..15
    int n   = rem & 255;         // 0..255
    int layer, c;
    if (gch < 4) { layer = 0; c = gch; } else { layer = 1 + (gch - 4) / 8; c = (gch - 4) % 8; }
    int k0 = c * KCH + 2 * kp;
    const float* W = (layer == 0) ? Wd : (Ws + (size_t)(layer - 1) * OUT * OUT);
    g_wt[u] = pack_h2(W[(size_t)k0 * OUT + n], W[(size_t)(k0 + 1) * OUT + n]);
}

// ---------------------------------------------------------------------------
// edge scatter: one warp per edge, red.global.add.v4.f32 into g_hbuf
// ---------------------------------------------------------------------------
__global__ void scatter_kernel(const float* __restrict__ x,
                               const float* __restrict__ rbf,
                               const void*  __restrict__ idxp,
                               const float* __restrict__ W_rbf,
                               int E) {
    const int lane = threadIdx.x & 31;
    const int c0   = lane * 4;
    float w[NRAD][4];
#pragma unroll
    for (int r = 0; r < NRAD; r++)
#pragma unroll
        for (int j = 0; j < 4; j++) w[r][j] = __ldg(&W_rbf[r * HIDDEN + c0 + j]);

    const bool is64 = (g_is64 != 0);
    const long long* i64 = (const long long*)idxp;
    const int*       i32 = (const int*)idxp;
    int warp  = (blockIdx.x * blockDim.x + threadIdx.x) >> 5;
    int nwarp = (gridDim.x * blockDim.x) >> 5;

    for (int e = warp; e < E; e += nwarp) {
        long long node = is64 ? __ldg(&i64[e]) : (long long)__ldg(&i32[e]);
        const float* rp = rbf + (size_t)e * NRAD;
        float r0 = __ldg(rp + 0), r1 = __ldg(rp + 1), r2 = __ldg(rp + 2);
        float r3 = __ldg(rp + 3), r4 = __ldg(rp + 4), r5 = __ldg(rp + 5);
        float4 xv = __ldcs((const float4*)(x + (size_t)e * HIDDEN + c0));
        float d[4];
#pragma unroll
        for (int j = 0; j < 4; j++) {
            float s = r0 * w[0][j];
            s = fmaf(r1, w[1][j], s); s = fmaf(r2, w[2][j], s);
            s = fmaf(r3, w[3][j], s); s = fmaf(r4, w[4][j], s);
            s = fmaf(r5, w[5][j], s);
            d[j] = s;
        }
        float g0 = d[0]*xv.x, g1 = d[1]*xv.y, g2 = d[2]*xv.z, g3 = d[3]*xv.w;
        float* dst = g_hbuf + (size_t)node * HIDDEN + c0;
        asm volatile("red.global.add.v4.f32 [%0], {%1,%2,%3,%4};"
                     :: "l"(dst), "f"(g0), "f"(g1), "f"(g2), "f"(g3) : "memory");
    }
}

// ---------------------------------------------------------------------------
// fused 4-layer MLP: fp16 m16n8k16 mma.sync, fp32 accum, cp.async
// double-buffered 16KB weight chunks. CTA tile 128x256, 8 warps 2(M)x4(N).
// Activations packed half2 in SMEM (k-pairs along columns).
// ---------------------------------------------------------------------------
__global__ __launch_bounds__(256, 1)
void mlp_kernel(const float* __restrict__ bs, float* __restrict__ out, int n_nodes) {
    extern __shared__ uint32_t smem[];
    uint32_t* As = smem;                           // [128][ASTRIDE2] half2
    uint32_t* Bs = smem + TM * ASTRIDE2;           // [2][KPC][BSTRIDE2] half2
    const uint32_t bs_smem = smem_u32(Bs);

    const int tid  = threadIdx.x;
    const int row0 = blockIdx.x * TM;

    // load activation tile, pack to half2 (k even, k odd)
    for (int t = tid; t < TM * (HIDDEN / 4); t += 256) {
        int r  = t >> 5;
        int c4 = (t & 31) << 2;
        float4 v = make_float4(0.f, 0.f, 0.f, 0.f);
        if (row0 + r < n_nodes)
            v = *(const float4*)(g_hbuf + (size_t)(row0 + r) * HIDDEN + c4);
        uint32_t* d = As + r * ASTRIDE2 + (c4 >> 1);
        d[0] = pack_h2(v.x, v.y);
        d[1] = pack_h2(v.z, v.w);
    }
    __syncthreads();

    const int lane = tid & 31;
    const int w    = tid >> 5;
    const int wm   = (w & 1) << 6;
    const int wn   = (w >> 1) << 6;
    const int g    = lane >> 2;
    const int q    = lane & 3;

    // stage one 16KB chunk: 1024 x 16B, 4 per thread.
    // chunk row = 256 u32 (1024B); SMEM row stride = BSTRIDE2 u32 (>=256).
    auto stage = [&](int gchunk, int buf) {
        const char* src = (const char*)(g_wt + (size_t)gchunk * CHUNK_U32);
#pragma unroll
        for (int j = 0; j < 4; j++) {
            int idx  = tid + j * 256;
            int row  = idx >> 6;          // 0..15 (k-pair)
            int c16  = idx & 63;          // 16B unit within 1KB row
            uint32_t dst = bs_smem
                         + (uint32_t)(buf * KPC * BSTRIDE2 + row * BSTRIDE2) * 4 + c16 * 16;
            cp_async16(dst, src + row * 1024 + c16 * 16);
        }
        cp_commit();
    };

    for (int layer = 0; layer < 4; layer++) {
        const int K   = (layer == 0) ? HIDDEN : OUT;
        const int nch = K / KCH;
        const int cb  = (layer == 0) ? 0 : (4 + (layer - 1) * 8);

        float C[4][8][4];
#pragma unroll
        for (int mi = 0; mi < 4; mi++)
#pragma unroll
            for (int ni = 0; ni < 8; ni++)
#pragma unroll
                for (int j = 0; j < 4; j++) C[mi][ni][j] = 0.f;

        stage(cb, 0);
        for (int c = 0; c < nch; c++) {
            const int buf = c & 1;
            if (c + 1 < nch) { stage(cb + c + 1, buf ^ 1); cp_wait<1>(); }
            else             { cp_wait<0>(); }
            __syncthreads();

            const uint32_t* B = Bs + buf * KPC * BSTRIDE2;
#pragma unroll
            for (int ks2 = 0; ks2 < KPC; ks2 += 8) {      // two k16 steps per chunk
                const int kpA = c * KPC + ks2;            // global k-pair base in As
                uint32_t a[4][4];
#pragma unroll
                for (int mi = 0; mi < 4; mi++) {
                    int r = wm + mi * 16 + g;
                    a[mi][0] = As[r * ASTRIDE2 + kpA + q];
                    a[mi][1] = As[(r + 8) * ASTRIDE2 + kpA + q];
                    a[mi][2] = As[r * ASTRIDE2 + kpA + q + 4];
                    a[mi][3] = As[(r + 8) * ASTRIDE2 + kpA + q + 4];
                }
                uint32_t b[8][2];
#pragma unroll
                for (int ni = 0; ni < 8; ni++) {
                    int cc = wn + ni * 8 + g;
                    b[ni][0] = B[(ks2 + q) * BSTRIDE2 + cc];
                    b[ni][1] = B[(ks2 + q + 4) * BSTRIDE2 + cc];
                }
#pragma unroll
                for (int mi = 0; mi < 4; mi++)
#pragma unroll
                    for (int ni = 0; ni < 8; ni++)
                        mma16(C[mi][ni], a[mi], b[ni]);
            }
            __syncthreads();   // buf consumed; safe for restage at c+2
        }

        float bias[8][2];
        if (layer > 0) {
            const float* bp = bs + (size_t)(layer - 1) * OUT;
#pragma unroll
            for (int ni = 0; ni < 8; ni++) {
                int cc = wn + ni * 8 + (q << 1);
                bias[ni][0] = __ldg(bp + cc);
                bias[ni][1] = __ldg(bp + cc + 1);
            }
        }

        // epilogue: bias + SiLU (layers 1-3); pack to As (0-2) or write gmem (3)
        // c0,c1 = (row g, cols 2q,2q+1); c2,c3 = (row g+8, same cols)
#pragma unroll
        for (int mi = 0; mi < 4; mi++) {
#pragma unroll
            for (int ni = 0; ni < 8; ni++) {
                float v[4];
#pragma unroll
                for (int j = 0; j < 4; j++) {
                    float xv = C[mi][ni][j];
                    if (layer > 0) {
                        xv += bias[ni][j & 1];
                        xv = xv / (1.f + __expf(-xv));
                    }
                    v[j] = xv;
                }
                int r  = wm + mi * 16 + g;
                int cc = wn + ni * 8 + (q << 1);
                if (layer < 3) {
                    As[r * ASTRIDE2 + (cc >> 1)]       = pack_h2(v[0], v[1]);
                    As[(r + 8) * ASTRIDE2 + (cc >> 1)] = pack_h2(v[2], v[3]);
                } else {
                    if (row0 + r < n_nodes)
                        *(float2*)(out + (size_t)(row0 + r) * OUT + cc) = make_float2(v[0], v[1]);
                    if (row0 + r + 8 < n_nodes)
                        *(float2*)(out + (size_t)(row0 + r + 8) * OUT + cc) = make_float2(v[2], v[3]);
                }
            }
        }
        __syncthreads();
    }
}

// ---------------------------------------------------------------------------
extern "C" void kernel_launch(void* const* d_in, const int* in_sizes, int n_in,
                              void* d_out, int out_size) {
    const float* x      = (const float*)d_in[0];
    const float* rbf    = (const float*)d_in[1];
    const void*  idx    = d_in[2];
    const float* W_rbf  = (const float*)d_in[3];
    const float* W_down = (const float*)d_in[4];
    const float* Ws     = (const float*)d_in[5];
    const float* bs     = (const float*)d_in[6];
    float* out = (float*)d_out;

    const int E       = in_sizes[0] / HIDDEN;
    const int n_nodes = out_size / OUT;

    void* hbuf_ptr = nullptr;
    cudaGetSymbolAddress(&hbuf_ptr, g_hbuf);
    cudaMemsetAsync(hbuf_ptr, 0, (size_t)n_nodes * HIDDEN * sizeof(float));

    prep_kernel<<<(NCHUNKS * CHUNK_U32 + 255) / 256, 256>>>(
        W_down, Ws, (const long long*)idx, n_nodes);
    scatter_kernel<<<2048, 256>>>(x, rbf, idx, W_rbf, E);

    const int smem_bytes = (TM * ASTRIDE2 + 2 * KPC * BSTRIDE2) * (int)sizeof(uint32_t);
    cudaFuncSetAttribute(mlp_kernel, cudaFuncAttributeMaxDynamicSharedMemorySize, smem_bytes);
    const int grid = (n_nodes + TM - 1) / TM;
    mlp_kernel<<<grid, 256, smem_bytes>>>(bs, out, n_nodes);
}

// round 15
// speedup vs baseline: 1.7417x; 1.2186x over previous
#include <cuda_runtime.h>
#include <cuda_fp16.h>
#include <cstdint>

#define HIDDEN   128
#define OUT      256
#define NRAD     6
#define TM       64                 // rows per CTA tile (2 CTAs/SM)
#define KCH      64                 // K elements per chunk
#define KPC      (KCH/2)            // 32 k-pairs per chunk
#define ASTRIDE2 132   // u32 stride, mod 32 = 4 -> a-frag banks 4g+q distinct
#define BSTRIDE2 264   // u32 stride (>=256 cols), mod 32 = 8 -> b-frag banks 8q+g distinct
#define CHUNK_U32 (KPC * OUT)       // 8192 u32 = 32KB per chunk image
#define NCHUNKS  14                 // 2 (layer0 K=128) + 3*4 (K=256)
#define NODES_MAX 50176

__device__ float    g_hbuf[(size_t)NODES_MAX * HIDDEN];   // scatter accumulator
__device__ uint32_t g_wt[(size_t)NCHUNKS * CHUNK_U32];    // fp16x2 weights [chunk][kpair][n]
__device__ int      g_is64;

__device__ __forceinline__ void cp_async16(uint32_t dst_smem, const void* src) {
    asm volatile("cp.async.cg.shared.global [%0], [%1], 16;" :: "r"(dst_smem), "l"(src) : "memory");
}
__device__ __forceinline__ void cp_commit() {
    asm volatile("cp.async.commit_group;" ::: "memory");
}
template <int N>
__device__ __forceinline__ void cp_wait() {
    asm volatile("cp.async.wait_group %0;" :: "n"(N) : "memory");
}
__device__ __forceinline__ uint32_t smem_u32(const void* p) {
    uint32_t a;
    asm("{ .reg .u64 t; cvta.to.shared.u64 t, %1; cvt.u32.u64 %0, t; }" : "=r"(a) : "l"(p));
    return a;
}
// m16n8k16 fp16 inputs, fp32 accumulate
__device__ __forceinline__ void mma16(float* c, const uint32_t* a, const uint32_t* b) {
    asm volatile("mma.sync.aligned.m16n8k16.row.col.f32.f16.f16.f32 "
                 "{%0,%1,%2,%3}, {%4,%5,%6,%7}, {%8,%9}, {%0,%1,%2,%3};"
                 : "+f"(c[0]), "+f"(c[1]), "+f"(c[2]), "+f"(c[3])
                 : "r"(a[0]), "r"(a[1]), "r"(a[2]), "r"(a[3]),
                   "r"(b[0]), "r"(b[1]));
}
__device__ __forceinline__ uint32_t pack_h2(float lo, float hi) {
    __half2 h = __floats2half2_rn(lo, hi);
    return *(uint32_t*)&h;
}

// ---------------------------------------------------------------------------
// prep: (a) index dtype detection; (b) weights -> fp16x2 k-pair-packed chunk
// images: g_wt[chunk][kpair][n] = half2(W[k0+2kp][n], W[k0+2kp+1][n]).
// ---------------------------------------------------------------------------
__global__ void prep_kernel(const float* __restrict__ Wd, const float* __restrict__ Ws,
                            const long long* __restrict__ idx, int n_nodes) {
    if (blockIdx.x == 0 && threadIdx.x < 32) {
        long long v = idx[threadIdx.x];
        unsigned ok = __ballot_sync(0xFFFFFFFFu, v >= 0 && v < (long long)n_nodes);
        if (threadIdx.x == 0) g_is64 = (ok == 0xFFFFFFFFu) ? 1 : 0;
    }
    int u = blockIdx.x * blockDim.x + threadIdx.x;
    if (u >= NCHUNKS * CHUNK_U32) return;
    int gch = u / CHUNK_U32;
    int rem = u % CHUNK_U32;
    int kp  = rem >> 8;          // 0..31
    int n   = rem & 255;         // 0..255
    int layer, c;
    if (gch < 2) { layer = 0; c = gch; } else { layer = 1 + (gch - 2) / 4; c = (gch - 2) % 4; }
    int k0 = c * KCH + 2 * kp;
    const float* W = (layer == 0) ? Wd : (Ws + (size_t)(layer - 1) * OUT * OUT);
    g_wt[u] = pack_h2(W[(size_t)k0 * OUT + n], W[(size_t)(k0 + 1) * OUT + n]);
}

// ---------------------------------------------------------------------------
// edge scatter: one warp per edge, red.global.add.v4.f32 into g_hbuf
// ---------------------------------------------------------------------------
__global__ void scatter_kernel(const float* __restrict__ x,
                               const float* __restrict__ rbf,
                               const void*  __restrict__ idxp,
                               const float* __restrict__ W_rbf,
                               int E) {
    const int lane = threadIdx.x & 31;
    const int c0   = lane * 4;
    float w[NRAD][4];
#pragma unroll
    for (int r = 0; r < NRAD; r++)
#pragma unroll
        for (int j = 0; j < 4; j++) w[r][j] = __ldg(&W_rbf[r * HIDDEN + c0 + j]);

    const bool is64 = (g_is64 != 0);
    const long long* i64 = (const long long*)idxp;
    const int*       i32 = (const int*)idxp;
    int warp  = (blockIdx.x * blockDim.x + threadIdx.x) >> 5;
    int nwarp = (gridDim.x * blockDim.x) >> 5;

    for (int e = warp; e < E; e += nwarp) {
        long long node = is64 ? __ldg(&i64[e]) : (long long)__ldg(&i32[e]);
        const float* rp = rbf + (size_t)e * NRAD;
        float r0 = __ldg(rp + 0), r1 = __ldg(rp + 1), r2 = __ldg(rp + 2);
        float r3 = __ldg(rp + 3), r4 = __ldg(rp + 4), r5 = __ldg(rp + 5);
        float4 xv = __ldcs((const float4*)(x + (size_t)e * HIDDEN + c0));
        float d[4];
#pragma unroll
        for (int j = 0; j < 4; j++) {
            float s = r0 * w[0][j];
            s = fmaf(r1, w[1][j], s); s = fmaf(r2, w[2][j], s);
            s = fmaf(r3, w[3][j], s); s = fmaf(r4, w[4][j], s);
            s = fmaf(r5, w[5][j], s);
            d[j] = s;
        }
        float g0 = d[0]*xv.x, g1 = d[1]*xv.y, g2 = d[2]*xv.z, g3 = d[3]*xv.w;
        float* dst = g_hbuf + (size_t)node * HIDDEN + c0;
        asm volatile("red.global.add.v4.f32 [%0], {%1,%2,%3,%4};"
                     :: "l"(dst), "f"(g0), "f"(g1), "f"(g2), "f"(g3) : "memory");
    }
}

// ---------------------------------------------------------------------------
// fused 4-layer MLP: fp16 m16n8k16 mma.sync, fp32 accum.
// CTA tile 64x256, 8 warps 2(M)x4(N), warp tile 32x64, 2 CTAs/SM.
// 32KB weight chunks, double-buffered cp.async with CROSS-LAYER prefetch
// (B staging is independent of the activation tile, so the next chunk is
// always in flight, including across layer boundaries / epilogues).
// ---------------------------------------------------------------------------
__global__ __launch_bounds__(256, 2)
void mlp_kernel(const float* __restrict__ bs, float* __restrict__ out, int n_nodes) {
    extern __shared__ uint32_t smem[];
    uint32_t* As = smem;                           // [64][ASTRIDE2] half2
    uint32_t* Bs = smem + TM * ASTRIDE2;           // [2][KPC][BSTRIDE2] half2
    const uint32_t bs_smem = smem_u32(Bs);

    const int tid  = threadIdx.x;
    const int row0 = blockIdx.x * TM;

    // stage one 32KB chunk: 2048 x 16B, 8 per thread. buf parity = global chunk idx.
    auto stage = [&](int gchunk) {
        const int buf = gchunk & 1;
        const char* src = (const char*)(g_wt + (size_t)gchunk * CHUNK_U32);
#pragma unroll
        for (int j = 0; j < 8; j++) {
            int idx  = tid + j * 256;
            int row  = idx >> 6;          // 0..31 (k-pair)
            int c16  = idx & 63;          // 16B unit within 1KB row
            uint32_t dst = bs_smem
                         + (uint32_t)(buf * KPC * BSTRIDE2 + row * BSTRIDE2) * 4 + c16 * 16;
            cp_async16(dst, src + row * 1024 + c16 * 16);
        }
        cp_commit();
    };

    stage(0);   // chunk 0 in flight while we load the activation tile

    // load activation tile, pack to half2 (k even, k odd)
    for (int t = tid; t < TM * (HIDDEN / 4); t += 256) {
        int r  = t >> 5;
        int c4 = (t & 31) << 2;
        float4 v = make_float4(0.f, 0.f, 0.f, 0.f);
        if (row0 + r < n_nodes)
            v = *(const float4*)(g_hbuf + (size_t)(row0 + r) * HIDDEN + c4);
        uint32_t* d = As + r * ASTRIDE2 + (c4 >> 1);
        d[0] = pack_h2(v.x, v.y);
        d[1] = pack_h2(v.z, v.w);
    }
    __syncthreads();

    const int lane = tid & 31;
    const int w    = tid >> 5;
    const int wm   = (w & 1) << 5;   // warp M offset: 0/32
    const int wn   = (w >> 1) << 6;  // warp N offset: 0/64/128/192
    const int g    = lane >> 2;
    const int q    = lane & 3;

    for (int layer = 0; layer < 4; layer++) {
        const int nch = (layer == 0) ? 2 : 4;
        const int cb  = (layer == 0) ? 0 : (2 + (layer - 1) * 4);

        float C[2][8][4];
#pragma unroll
        for (int mi = 0; mi < 2; mi++)
#pragma unroll
            for (int ni = 0; ni < 8; ni++)
#pragma unroll
                for (int j = 0; j < 4; j++) C[mi][ni][j] = 0.f;

        for (int c = 0; c < nch; c++) {
            const int gc  = cb + c;
            const int buf = gc & 1;
            if (gc + 1 < NCHUNKS) { stage(gc + 1); cp_wait<1>(); }
            else                  { cp_wait<0>(); }
            __syncthreads();

            const uint32_t* B = Bs + buf * KPC * BSTRIDE2;
#pragma unroll
            for (int ks2 = 0; ks2 < KPC; ks2 += 8) {      // 4 k16-steps per chunk
                const int kpA = c * KPC + ks2;            // global k-pair base in As
                uint32_t a[2][4];
#pragma unroll
                for (int mi = 0; mi < 2; mi++) {
                    int r = wm + mi * 16 + g;
                    a[mi][0] = As[r * ASTRIDE2 + kpA + q];
                    a[mi][1] = As[(r + 8) * ASTRIDE2 + kpA + q];
                    a[mi][2] = As[r * ASTRIDE2 + kpA + q + 4];
                    a[mi][3] = As[(r + 8) * ASTRIDE2 + kpA + q + 4];
                }
                uint32_t b[8][2];
#pragma unroll
                for (int ni = 0; ni < 8; ni++) {
                    int cc = wn + ni * 8 + g;
                    b[ni][0] = B[(ks2 + q) * BSTRIDE2 + cc];
                    b[ni][1] = B[(ks2 + q + 4) * BSTRIDE2 + cc];
                }
#pragma unroll
                for (int mi = 0; mi < 2; mi++)
#pragma unroll
                    for (int ni = 0; ni < 8; ni++)
                        mma16(C[mi][ni], a[mi], b[ni]);
            }
            __syncthreads();   // buf consumed; safe for restage
        }

        float bias[8][2];
        if (layer > 0) {
            const float* bp = bs + (size_t)(layer - 1) * OUT;
#pragma unroll
            for (int ni = 0; ni < 8; ni++) {
                int cc = wn + ni * 8 + (q << 1);
                bias[ni][0] = __ldg(bp + cc);
                bias[ni][1] = __ldg(bp + cc + 1);
            }
        }

        // epilogue: bias + SiLU (layers 1-3); pack to As (0-2) or write gmem (3)
#pragma unroll
        for (int mi = 0; mi < 2; mi++) {
#pragma unroll
            for (int ni = 0; ni < 8; ni++) {
                float v[4];
#pragma unroll
                for (int j = 0; j < 4; j++) {
                    float xv = C[mi][ni][j];
                    if (layer > 0) {
                        xv += bias[ni][j & 1];
                        xv = xv / (1.f + __expf(-xv));
                    }
                    v[j] = xv;
                }
                int r  = wm + mi * 16 + g;
                int cc = wn + ni * 8 + (q << 1);
                if (layer < 3) {
                    As[r * ASTRIDE2 + (cc >> 1)]       = pack_h2(v[0], v[1]);
                    As[(r + 8) * ASTRIDE2 + (cc >> 1)] = pack_h2(v[2], v[3]);
                } else {
                    if (row0 + r < n_nodes)
                        *(float2*)(out + (size_t)(row0 + r) * OUT + cc) = make_float2(v[0], v[1]);
                    if (row0 + r + 8 < n_nodes)
                        *(float2*)(out + (size_t)(row0 + r + 8) * OUT + cc) = make_float2(v[2], v[3]);
                }
            }
        }
        __syncthreads();
    }
}

// ---------------------------------------------------------------------------
extern "C" void kernel_launch(void* const* d_in, const int* in_sizes, int n_in,
                              void* d_out, int out_size) {
    const float* x      = (const float*)d_in[0];
    const float* rbf    = (const float*)d_in[1];
    const void*  idx    = d_in[2];
    const float* W_rbf  = (const float*)d_in[3];
    const float* W_down = (const float*)d_in[4];
    const float* Ws     = (const float*)d_in[5];
    const float* bs     = (const float*)d_in[6];
    float* out = (float*)d_out;

    const int E       = in_sizes[0] / HIDDEN;
    const int n_nodes = out_size / OUT;

    void* hbuf_ptr = nullptr;
    cudaGetSymbolAddress(&hbuf_ptr, g_hbuf);
    cudaMemsetAsync(hbuf_ptr, 0, (size_t)n_nodes * HIDDEN * sizeof(float));

    prep_kernel<<<(NCHUNKS * CHUNK_U32 + 255) / 256, 256>>>(
        W_down, Ws, (const long long*)idx, n_nodes);
    scatter_kernel<<<2048, 256>>>(x, rbf, idx, W_rbf, E);

    const int smem_bytes = (TM * ASTRIDE2 + 2 * KPC * BSTRIDE2) * (int)sizeof(uint32_t);
    cudaFuncSetAttribute(mlp_kernel, cudaFuncAttributeMaxDynamicSharedMemorySize, smem_bytes);
    const int grid = (n_nodes + TM - 1) / TM;
    mlp_kernel<<<grid, 256, smem_bytes>>>(bs, out, n_nodes);
}